// round 3
// baseline (speedup 1.0000x reference)
#include <cuda_runtime.h>
#include <math.h>

#define BB   4
#define NN   4096
#define DIN  256
#define DOUT 128
#define NEG_BIG (-9e15f)

// ---------------- scratch (__device__ globals: allocation-free) -------------
__device__ float g_h[BB * NN * DOUT];       // 8 MB  : h = x @ W
__device__ float g_wh1[BB * NN];            // per-row score term
__device__ float g_wh2[BB * NN];            // per-col score term
__device__ float g_pm[BB * 8 * NN];         // partial col-max (8 chunks)
__device__ float g_pz[BB * 8 * NN];         // partial col-sum
__device__ float g_m[BB * NN];              // col max
__device__ float g_iz[BB * NN];             // 1/col-sum
__device__ float g_ss[BB * DOUT];           // per-(b,d) sum of squares

__device__ __forceinline__ float gelu_f(float x) {
    return 0.5f * x * (1.0f + erff(x * 0.70710678118654752f));
}

// ---------------- K0: zero the sumsq accumulator ----------------------------
__global__ void k0_zero() {
    int t = threadIdx.x;
    if (t < BB * DOUT) g_ss[t] = 0.0f;
}

// ---------------- K1: h = x @ W  (M=16384, K=256, N=128) --------------------
// 128x128 tile, 256 threads, 8x8 micro-tile, BK=32.
__global__ __launch_bounds__(256) void k1_h(const float* __restrict__ x,
                                            const float* __restrict__ w) {
    __shared__ float xsT[32 * 129];   // [k][row], padded
    __shared__ float ws[32 * 128];    // [k][d]
    const int t = threadIdx.x, lane = t & 31, wrp = t >> 5;
    const int ty = t >> 4, tx = t & 15;
    const int i0 = blockIdx.x * 128;

    float acc[8][8];
#pragma unroll
    for (int r = 0; r < 8; r++)
#pragma unroll
        for (int c = 0; c < 8; c++) acc[r][c] = 0.0f;

    for (int kk = 0; kk < DIN; kk += 32) {
        // stage x tile (transposed): warp reads 32 consecutive floats per row
#pragma unroll
        for (int s = 0; s < 16; s++) {
            int ii = wrp + 8 * s;
            xsT[lane * 129 + ii] = x[(i0 + ii) * DIN + kk + lane];
        }
        // stage W tile
#pragma unroll
        for (int s = 0; s < 16; s++) {
            int idx = t + s * 256;
            int k = idx >> 7, d = idx & 127;
            ws[k * 128 + d] = w[(kk + k) * DOUT + d];
        }
        __syncthreads();
#pragma unroll
        for (int k = 0; k < 32; k++) {
            float aa[8];
#pragma unroll
            for (int r = 0; r < 8; r++) aa[r] = xsT[k * 129 + ty * 8 + r];
            float4 b0 = *(const float4*)&ws[k * 128 + tx * 8];
            float4 b1 = *(const float4*)&ws[k * 128 + tx * 8 + 4];
            float bb[8] = {b0.x, b0.y, b0.z, b0.w, b1.x, b1.y, b1.z, b1.w};
#pragma unroll
            for (int r = 0; r < 8; r++)
#pragma unroll
                for (int c = 0; c < 8; c++)
                    acc[r][c] = fmaf(aa[r], bb[c], acc[r][c]);
        }
        __syncthreads();
    }
#pragma unroll
    for (int r = 0; r < 8; r++) {
        int row = i0 + ty * 8 + r;
        float4 o0, o1;
        o0.x = acc[r][0]; o0.y = acc[r][1]; o0.z = acc[r][2]; o0.w = acc[r][3];
        o1.x = acc[r][4]; o1.y = acc[r][5]; o1.z = acc[r][6]; o1.w = acc[r][7];
        *(float4*)&g_h[row * DOUT + tx * 8]     = o0;
        *(float4*)&g_h[row * DOUT + tx * 8 + 4] = o1;
    }
}

// ---------------- K1b: Wh1 = h@a1, Wh2 = h@a2 (per-row dots) ----------------
__global__ __launch_bounds__(256) void k1b_wh(const float* __restrict__ a) {
    const int t = threadIdx.x, lane = t & 31, wrp = t >> 5;
    const int gw = blockIdx.x * 8 + wrp;           // 0..511
    for (int r0 = 0; r0 < 32; r0++) {
        int row = gw * 32 + r0;                    // 0..16383
        float s1 = 0.0f, s2 = 0.0f;
#pragma unroll
        for (int u = 0; u < 4; u++) {
            float hv = g_h[row * DOUT + lane + u * 32];
            s1 += hv * a[lane + u * 32];
            s2 += hv * a[DOUT + lane + u * 32];
        }
#pragma unroll
        for (int o = 16; o > 0; o >>= 1) {
            s1 += __shfl_xor_sync(0xffffffffu, s1, o);
            s2 += __shfl_xor_sync(0xffffffffu, s2, o);
        }
        if (lane == 0) { g_wh1[row] = s1; g_wh2[row] = s2; }
    }
}

// ---------------- K2a: per-column partial online softmax stats --------------
// Softmax is over axis i (rows) for each column j. Chunk the i range 8 ways.
// grid (32 col-blocks, 8 chunks, 4 batches), 128 threads, 1 thread = 1 column.
__global__ __launch_bounds__(128) void k2a_stats(const int* __restrict__ adj) {
    __shared__ float wh1s[128];
    const int t = threadIdx.x;
    const int b = blockIdx.z;
    const int cz = blockIdx.y;
    const int j = blockIdx.x * 128 + t;
    const float wh2j = g_wh2[b * NN + j];
    float m = NEG_BIG, z = 0.0f;
    const int rbase = cz * 512;
    for (int i0 = 0; i0 < 512; i0 += 128) {
        __syncthreads();
        wh1s[t] = g_wh1[b * NN + rbase + i0 + t];
        __syncthreads();
        const int* ap = adj + ((b * NN + rbase + i0) * NN + j);
        for (int ii = 0; ii < 128; ii += 8) {
            int av[8]; float wv[8];
#pragma unroll
            for (int u = 0; u < 8; u++) {          // batch loads for MLP=8
                av[u] = ap[(ii + u) * NN];
                wv[u] = wh1s[ii + u];
            }
#pragma unroll
            for (int u = 0; u < 8; u++) {
                if (av[u] > 0) {
                    float s = gelu_f(wv[u] + wh2j);
                    if (s > m) { z = z * __expf(m - s) + 1.0f; m = s; }
                    else       { z += __expf(s - m); }
                }
            }
        }
    }
    g_pm[(b * 8 + cz) * NN + j] = m;
    g_pz[(b * 8 + cz) * NN + j] = z;
}

// ---------------- K2b: combine partial stats --------------------------------
__global__ __launch_bounds__(128) void k2b_combine() {
    int c = blockIdx.x * 128 + threadIdx.x;        // 0..16383 (= b*NN + j)
    int b = c >> 12, j = c & (NN - 1);
    float M = NEG_BIG;
#pragma unroll
    for (int u = 0; u < 8; u++) M = fmaxf(M, g_pm[(b * 8 + u) * NN + j]);
    float Z = 0.0f;
#pragma unroll
    for (int u = 0; u < 8; u++)
        Z += g_pz[(b * 8 + u) * NN + j] * __expf(g_pm[(b * 8 + u) * NN + j] - M);
    g_m[c] = M;
    g_iz[c] = 1.0f / fmaxf(Z, 1e-37f);             // unused when column fully masked
}

// ---------------- K3: out = gelu(attn @ h), attn recomputed on the fly ------
// 128(i) x 128(d) tile per block, K(=j) chunks of 32. 256 thr, 8x8 micro-tile.
__global__ __launch_bounds__(256) void k3_pv(const int* __restrict__ adj,
                                             float* __restrict__ out) {
    __shared__ float hs[32 * 128];     // [k][d] — same layout as gmem chunk
    __shared__ float asT[32 * 129];    // [k][i], padded for bank-conflict-free
    __shared__ float wh1s[128];
    const int t = threadIdx.x, lane = t & 31, wrp = t >> 5;
    const int ty = t >> 4, tx = t & 15;
    const int b = blockIdx.y;
    const int i0 = blockIdx.x * 128;

    if (t < 128) wh1s[t] = g_wh1[b * NN + i0 + t];

    float acc[8][8];
#pragma unroll
    for (int r = 0; r < 8; r++)
#pragma unroll
        for (int c = 0; c < 8; c++) acc[r][c] = 0.0f;
    __syncthreads();

    for (int kb = 0; kb < NN; kb += 32) {
        // per-lane column constants (lane <-> k within the chunk)
        const int jj = kb + lane;
        const float wh2v = g_wh2[b * NN + jj];
        const float mv   = g_m[b * NN + jj];
        const float izv  = g_iz[b * NN + jj];

        // stage h chunk (contiguous 32x128 floats -> linear float4 copy)
        {
            const float4* hsrc = (const float4*)(g_h + (b * NN + kb) * DOUT);
            float4* hdst = (float4*)hs;
#pragma unroll
            for (int s = 0; s < 4; s++) hdst[t + s * 256] = hsrc[t + s * 256];
        }
        // stage attn tile: adj loads batched (MLP=16), then score->softmax weight
        {
            const int* ap = adj + ((b * NN + i0) * NN + kb);
            int av[16];
#pragma unroll
            for (int s = 0; s < 16; s++) av[s] = ap[(wrp + 8 * s) * NN + lane];
#pragma unroll
            for (int s = 0; s < 16; s++) {
                int ii = wrp + 8 * s;
                float v = 0.0f;
                if (av[s] > 0)
                    v = __expf(gelu_f(wh1s[ii] + wh2v) - mv) * izv;
                asT[lane * 129 + ii] = v;       // bank (lane+ii)%32: conflict-free
            }
        }
        __syncthreads();
#pragma unroll
        for (int k = 0; k < 32; k++) {
            float aa[8];
#pragma unroll
            for (int r = 0; r < 8; r++) aa[r] = asT[k * 129 + ty * 8 + r];
            float4 b0 = *(const float4*)&hs[k * 128 + tx * 8];
            float4 b1 = *(const float4*)&hs[k * 128 + tx * 8 + 4];
            float bb[8] = {b0.x, b0.y, b0.z, b0.w, b1.x, b1.y, b1.z, b1.w};
#pragma unroll
            for (int r = 0; r < 8; r++)
#pragma unroll
                for (int c = 0; c < 8; c++)
                    acc[r][c] = fmaf(aa[r], bb[c], acc[r][c]);
        }
        __syncthreads();
    }
    // epilogue: gelu + store
#pragma unroll
    for (int r = 0; r < 8; r++) {
        int row = i0 + ty * 8 + r;
        float4 o0, o1;
        o0.x = gelu_f(acc[r][0]); o0.y = gelu_f(acc[r][1]);
        o0.z = gelu_f(acc[r][2]); o0.w = gelu_f(acc[r][3]);
        o1.x = gelu_f(acc[r][4]); o1.y = gelu_f(acc[r][5]);
        o1.z = gelu_f(acc[r][6]); o1.w = gelu_f(acc[r][7]);
        *(float4*)&out[(b * NN + row) * DOUT + tx * 8]     = o0;
        *(float4*)&out[(b * NN + row) * DOUT + tx * 8 + 4] = o1;
    }
}

// ---------------- K4: sum of squares over node axis per (b,d) ---------------
__global__ __launch_bounds__(128) void k4_sumsq(const float* __restrict__ out) {
    const int t = threadIdx.x;                     // = d
    const int b = blockIdx.y;
    const int ibase = blockIdx.x * 256;
    float s = 0.0f;
    for (int i = 0; i < 256; i++) {
        float v = out[(b * NN + ibase + i) * DOUT + t];
        s += v * v;
    }
    atomicAdd(&g_ss[b * DOUT + t], s);
}

// ---------------- K5: L2-normalize over node axis + bias --------------------
__global__ __launch_bounds__(256) void k5_norm(float* __restrict__ out,
                                               const float* __restrict__ bias) {
    int idx = blockIdx.x * 256 + threadIdx.x;      // < 4*4096*128 = 2^21
    int d = idx & 127;
    int b = idx >> 19;                             // 4096*128 = 2^19 per batch
    float ss = g_ss[b * DOUT + d];
    float inv = 1.0f / fmaxf(sqrtf(ss), 1e-12f);
    out[idx] = out[idx] * inv + bias[d];
}

// ---------------- launch ----------------------------------------------------
extern "C" void kernel_launch(void* const* d_in, const int* in_sizes, int n_in,
                              void* d_out, int out_size) {
    const float* x    = (const float*)d_in[0];   // [4,4096,256]
    const int*   adj  = (const int*)d_in[1];     // [4,4096,4096]
    const float* w    = (const float*)d_in[2];   // [256,128]
    const float* a    = (const float*)d_in[3];   // [256,1]
    const float* bias = (const float*)d_in[4];   // [128]
    float* out = (float*)d_out;                  // [4,4096,128] fp32

    k0_zero<<<1, 512>>>();
    k1_h<<<128, 256>>>(x, w);
    k1b_wh<<<64, 256>>>(a);
    k2a_stats<<<dim3(32, 8, BB), 128>>>(adj);
    k2b_combine<<<128, 128>>>();
    k3_pv<<<dim3(32, BB), 256>>>(adj, out);
    k4_sumsq<<<dim3(16, BB), 128>>>(out);
    k5_norm<<<8192, 256>>>(out, bias);
}

// round 6
// speedup vs baseline: 1.1794x; 1.1794x over previous
#include <cuda_runtime.h>
#include <math.h>
#include <stdint.h>

#define BB   4
#define NN   4096
#define DIN  256
#define DOUT 128

// ---------------- scratch (__device__ globals: allocation-free) -------------
__device__ float g_h [BB * NN * DOUT];      // 8 MB : h = x @ W   ([b][i][d])
__device__ float g_hT[BB * DOUT * NN];      // 8 MB : transposed  ([b][d][i])
__device__ float g_wh1[BB * NN];
__device__ float g_wh2[BB * NN];
__device__ float g_mw1[BB];                 // per-batch max of wh1
__device__ float g_pz[BB * 8 * NN];         // partial col-sums (8 chunks)
__device__ float g_c [BB * NN];             // per-col stabilizer
__device__ float g_iz[BB * NN];             // 1 / col-sum
__device__ float g_ss[BB * DOUT];           // per-(b,d) sum of squares

__device__ __forceinline__ float gelu_f(float x) {
    return 0.5f * x * (1.0f + erff(x * 0.70710678118654752f));
}
__device__ __forceinline__ uint32_t tf32u(float x) {
    uint32_t r; asm("cvt.rna.tf32.f32 %0, %1;" : "=r"(r) : "f"(x)); return r;
}
// m16n8k8 tf32 HMMA (baseline sm_80+ feature; valid on compute_103)
__device__ __forceinline__ void mma_tf32(float* d, const uint32_t* a, const uint32_t* b) {
    asm volatile("mma.sync.aligned.m16n8k8.row.col.f32.tf32.tf32.f32 "
                 "{%0,%1,%2,%3}, {%4,%5,%6,%7}, {%8,%9}, {%0,%1,%2,%3};"
                 : "+f"(d[0]), "+f"(d[1]), "+f"(d[2]), "+f"(d[3])
                 : "r"(a[0]), "r"(a[1]), "r"(a[2]), "r"(a[3]),
                   "r"(b[0]), "r"(b[1]));
}

// ---------------- K0: zero sumsq --------------------------------------------
__global__ void k0_zero() {
    int t = threadIdx.x;
    if (t < BB * DOUT) g_ss[t] = 0.0f;
}

// ---------------- K1: h = x @ W  (fp32 FFMA, full precision; ~1 GFLOP) ------
__global__ __launch_bounds__(256) void k1_h(const float* __restrict__ x,
                                            const float* __restrict__ w) {
    __shared__ float xsT[32 * 129];
    __shared__ float ws[32 * 128];
    const int t = threadIdx.x, lane = t & 31, wrp = t >> 5;
    const int ty = t >> 4, tx = t & 15;
    const int i0 = blockIdx.x * 128;

    float acc[8][8];
#pragma unroll
    for (int r = 0; r < 8; r++)
#pragma unroll
        for (int c = 0; c < 8; c++) acc[r][c] = 0.0f;

    for (int kk = 0; kk < DIN; kk += 32) {
#pragma unroll
        for (int s = 0; s < 16; s++) {
            int ii = wrp + 8 * s;
            xsT[lane * 129 + ii] = x[(i0 + ii) * DIN + kk + lane];
        }
#pragma unroll
        for (int s = 0; s < 16; s++) {
            int idx = t + s * 256;
            int k = idx >> 7, d = idx & 127;
            ws[k * 128 + d] = w[(kk + k) * DOUT + d];
        }
        __syncthreads();
#pragma unroll
        for (int k = 0; k < 32; k++) {
            float aa[8];
#pragma unroll
            for (int r = 0; r < 8; r++) aa[r] = xsT[k * 129 + ty * 8 + r];
            float4 b0 = *(const float4*)&ws[k * 128 + tx * 8];
            float4 b1 = *(const float4*)&ws[k * 128 + tx * 8 + 4];
            float bb[8] = {b0.x, b0.y, b0.z, b0.w, b1.x, b1.y, b1.z, b1.w};
#pragma unroll
            for (int r = 0; r < 8; r++)
#pragma unroll
                for (int c = 0; c < 8; c++)
                    acc[r][c] = fmaf(aa[r], bb[c], acc[r][c]);
        }
        __syncthreads();
    }
#pragma unroll
    for (int r = 0; r < 8; r++) {
        int row = i0 + ty * 8 + r;
        float4 o0, o1;
        o0.x = acc[r][0]; o0.y = acc[r][1]; o0.z = acc[r][2]; o0.w = acc[r][3];
        o1.x = acc[r][4]; o1.y = acc[r][5]; o1.z = acc[r][6]; o1.w = acc[r][7];
        *(float4*)&g_h[row * DOUT + tx * 8]     = o0;
        *(float4*)&g_h[row * DOUT + tx * 8 + 4] = o1;
    }
}

// ---------------- K1t: hT = transpose(h) per batch --------------------------
__global__ __launch_bounds__(256) void k1t_transpose() {
    __shared__ float ts[32][33];
    const int t = threadIdx.x, lx = t & 31, ly = t >> 5;
    const int i0 = blockIdx.x * 32, d0 = blockIdx.y * 32, b = blockIdx.z;
#pragma unroll
    for (int s = 0; s < 4; s++)
        ts[ly + 8 * s][lx] = g_h[(size_t)(b * NN + i0 + ly + 8 * s) * DOUT + d0 + lx];
    __syncthreads();
#pragma unroll
    for (int s = 0; s < 4; s++)
        g_hT[(size_t)(b * DOUT + d0 + ly + 8 * s) * NN + i0 + lx] = ts[lx][ly + 8 * s];
}

// ---------------- K1b: Wh1 = h@a1, Wh2 = h@a2 -------------------------------
__global__ __launch_bounds__(256) void k1b_wh(const float* __restrict__ a) {
    const int t = threadIdx.x, lane = t & 31, wrp = t >> 5;
    const int gw = blockIdx.x * 8 + wrp;
    for (int r0 = 0; r0 < 32; r0++) {
        int row = gw * 32 + r0;
        float s1 = 0.0f, s2 = 0.0f;
#pragma unroll
        for (int u = 0; u < 4; u++) {
            float hv = g_h[row * DOUT + lane + u * 32];
            s1 += hv * a[lane + u * 32];
            s2 += hv * a[DOUT + lane + u * 32];
        }
#pragma unroll
        for (int o = 16; o > 0; o >>= 1) {
            s1 += __shfl_xor_sync(0xffffffffu, s1, o);
            s2 += __shfl_xor_sync(0xffffffffu, s2, o);
        }
        if (lane == 0) { g_wh1[row] = s1; g_wh2[row] = s2; }
    }
}

// ---------------- K1c: maxWh1 per batch -------------------------------------
__global__ __launch_bounds__(1024) void k1c_max() {
    __shared__ float red[32];
    const int b = blockIdx.x, t = threadIdx.x, lane = t & 31, wrp = t >> 5;
    float m = -1e30f;
    for (int i = t; i < NN; i += 1024) m = fmaxf(m, g_wh1[b * NN + i]);
#pragma unroll
    for (int o = 16; o > 0; o >>= 1) m = fmaxf(m, __shfl_xor_sync(0xffffffffu, m, o));
    if (lane == 0) red[wrp] = m;
    __syncthreads();
    if (t < 32) {
        float v = red[t];
#pragma unroll
        for (int o = 16; o > 0; o >>= 1) v = fmaxf(v, __shfl_xor_sync(0xffffffffu, v, o));
        if (t == 0) g_mw1[b] = v;
    }
}

// ---------------- K2a: branchless per-column partial sums (int4 adj) --------
// stabilizer c_j = max(0, maxWh1 + wh2_j) >= gelu(wh1_i + wh2_j) always,
// so exp(s - c) <= 1 (no overflow) and no online-max needed.
__global__ __launch_bounds__(128) void k2a_stats(const int* __restrict__ adj) {
    __shared__ float wh1s[128];
    const int t = threadIdx.x;
    const int b = blockIdx.z, cz = blockIdx.y;
    const int j0 = (blockIdx.x * 128 + t) * 4;     // 4 columns per thread
    const int bN = b * NN;
    const float mw = g_mw1[b];
    float wh2v[4], cv[4], z[4];
#pragma unroll
    for (int u = 0; u < 4; u++) {
        wh2v[u] = g_wh2[bN + j0 + u];
        cv[u]   = fmaxf(0.0f, mw + wh2v[u]);
        z[u]    = 0.0f;
    }
    const int rbase = cz * 512;
    const int4* ap = (const int4*)(adj + (size_t)(bN + rbase) * NN) + (j0 >> 2);
    for (int i0 = 0; i0 < 512; i0 += 128) {
        __syncthreads();
        wh1s[t] = g_wh1[bN + rbase + i0 + t];
        __syncthreads();
        for (int ii = 0; ii < 128; ii += 4) {
            int4 a4[4]; float wv[4];
#pragma unroll
            for (int u = 0; u < 4; u++) {            // batch loads: MLP=4 int4
                a4[u] = ap[(size_t)(i0 + ii + u) * (NN / 4)];
                wv[u] = wh1s[ii + u];
            }
#pragma unroll
            for (int u = 0; u < 4; u++) {
                float e0 = __expf(gelu_f(wv[u] + wh2v[0]) - cv[0]);
                float e1 = __expf(gelu_f(wv[u] + wh2v[1]) - cv[1]);
                float e2 = __expf(gelu_f(wv[u] + wh2v[2]) - cv[2]);
                float e3 = __expf(gelu_f(wv[u] + wh2v[3]) - cv[3]);
                z[0] += (a4[u].x > 0) ? e0 : 0.0f;
                z[1] += (a4[u].y > 0) ? e1 : 0.0f;
                z[2] += (a4[u].z > 0) ? e2 : 0.0f;
                z[3] += (a4[u].w > 0) ? e3 : 0.0f;
            }
        }
    }
#pragma unroll
    for (int u = 0; u < 4; u++) g_pz[(b * 8 + cz) * NN + j0 + u] = z[u];
}

// ---------------- K2b: combine partials; store c_j, 1/Z_j -------------------
__global__ __launch_bounds__(128) void k2b_combine() {
    int c = blockIdx.x * 128 + threadIdx.x;        // b*NN + j
    int b = c >> 12;
    float Z = 0.0f;
#pragma unroll
    for (int u = 0; u < 8; u++) Z += g_pz[(b * 8 + u) * NN + (c & (NN - 1))];
    g_iz[c] = 1.0f / fmaxf(Z, 1e-37f);
    g_c[c]  = fmaxf(0.0f, g_mw1[b] + g_wh2[c]);
}

// ---------------- K3: out = gelu(attn @ h) via mma.sync tf32 ----------------
// Block: 128(i) x 128(d), K(=j) in chunks of 32, 8 warps (2m x 4n), each warp
// 64x32 as 4x4 m16n8k8 tiles. SMEM tiles padded to 36 floats/row so every
// fragment access has bank = (4*group + tig) % 32 -> conflict-free.
// Dynamic SMEM floats: [0..127] wh1s | A0 4608 | A1 4608 | B0 4608 | B1 4608
#define OFF_A0 128
#define OFF_A1 (128 + 4608)
#define OFF_B0 (128 + 2 * 4608)
#define OFF_B1 (128 + 3 * 4608)
#define SMEM_K3 ((128 + 4 * 4608) * 4)   // 74240 bytes

__device__ __forceinline__ void k3_fill(float* sm, int stage, int kt, int b, int i0,
                                        const int* __restrict__ adj,
                                        const float* __restrict__ wh1s,
                                        int t, int lane, int wrp) {
    const int kb = kt * 32;
    float* sA = sm + (stage ? OFF_A1 : OFF_A0);
    float* sB = sm + (stage ? OFF_B1 : OFF_B0);
    // ---- B tile: hT[d][kb..kb+31] -> tf32, [d][36] layout (coalesced LDG) --
    const float* hT = g_hT + (size_t)b * DOUT * NN;
#pragma unroll
    for (int s = 0; s < 4; s++) {
        int idx = t + s * 256;                   // 0..1023 float4s
        int d = idx >> 3, f4 = idx & 7;
        float4 v = *(const float4*)(hT + (size_t)d * NN + kb + f4 * 4);
        uint4 o; o.x = tf32u(v.x); o.y = tf32u(v.y); o.z = tf32u(v.z); o.w = tf32u(v.w);
        *(uint4*)(sB + d * 36 + f4 * 4) = o;
    }
    // ---- A tile: attn[i0..i0+127][kb..kb+31] recomputed, [i][36] layout ----
    const int bN = b * NN;
    const int j = kb + lane;
    const float wh2v = g_wh2[bN + j];
    const float cv   = g_c [bN + j];
    const float izv  = g_iz[bN + j];
    const int* ap = adj + (size_t)(bN + i0) * NN + j;
    int av[16];
#pragma unroll
    for (int s = 0; s < 16; s++) av[s] = ap[(size_t)(wrp + 8 * s) * NN];
#pragma unroll
    for (int s = 0; s < 16; s++) {
        int row = wrp + 8 * s;
        float v = 0.0f;
        if (av[s] > 0) v = __expf(gelu_f(wh1s[row] + wh2v) - cv) * izv;
        ((uint32_t*)sA)[row * 36 + lane] = tf32u(v);
    }
}

__global__ __launch_bounds__(256) void k3_pv(const int* __restrict__ adj,
                                             float* __restrict__ out) {
    extern __shared__ float sm[];
    const int t = threadIdx.x, lane = t & 31, wrp = t >> 5;
    const int g = lane >> 2, tg = lane & 3;           // fragment group / tid-in-group
    const int b = blockIdx.y;
    const int i0 = blockIdx.x * 128;
    const int m_base = (wrp >> 2) * 64;               // 2 warp-rows
    const int n_base = (wrp & 3) * 32;                // 4 warp-cols

    if (t < 128) sm[t] = g_wh1[b * NN + i0 + t];      // wh1s
    __syncthreads();

    float acc[4][4][4];
#pragma unroll
    for (int mt = 0; mt < 4; mt++)
#pragma unroll
        for (int nt = 0; nt < 4; nt++)
#pragma unroll
            for (int q = 0; q < 4; q++) acc[mt][nt][q] = 0.0f;

    k3_fill(sm, 0, 0, b, i0, adj, sm, t, lane, wrp);
    __syncthreads();

    for (int kt = 0; kt < 128; kt++) {
        const int cur = kt & 1;
        if (kt + 1 < 128)                              // overlap fill with mma
            k3_fill(sm, cur ^ 1, kt + 1, b, i0, adj, sm, t, lane, wrp);
        const uint32_t* sA = (const uint32_t*)(sm + (cur ? OFF_A1 : OFF_A0));
        const uint32_t* sB = (const uint32_t*)(sm + (cur ? OFF_B1 : OFF_B0));
#pragma unroll
        for (int ks = 0; ks < 4; ks++) {
            const int k0 = ks * 8;
            uint32_t af[4][4], bf[4][2];
#pragma unroll
            for (int mt = 0; mt < 4; mt++) {
                int r = m_base + mt * 16 + g;
                af[mt][0] = sA[r * 36 + k0 + tg];
                af[mt][1] = sA[(r + 8) * 36 + k0 + tg];
                af[mt][2] = sA[r * 36 + k0 + tg + 4];
                af[mt][3] = sA[(r + 8) * 36 + k0 + tg + 4];
            }
#pragma unroll
            for (int nt = 0; nt < 4; nt++) {
                int cc = n_base + nt * 8 + g;
                bf[nt][0] = sB[cc * 36 + k0 + tg];
                bf[nt][1] = sB[cc * 36 + k0 + tg + 4];
            }
#pragma unroll
            for (int mt = 0; mt < 4; mt++)
#pragma unroll
                for (int nt = 0; nt < 4; nt++)
                    mma_tf32(acc[mt][nt], af[mt], bf[nt]);
        }
        __syncthreads();
    }

    // epilogue: gelu + float2 stores (c0,c1 are adjacent columns)
#pragma unroll
    for (int mt = 0; mt < 4; mt++) {
        int r = i0 + m_base + mt * 16 + g;
#pragma unroll
        for (int nt = 0; nt < 4; nt++) {
            int cl = n_base + nt * 8 + 2 * tg;
            float2 v0, v1;
            v0.x = gelu_f(acc[mt][nt][0]); v0.y = gelu_f(acc[mt][nt][1]);
            v1.x = gelu_f(acc[mt][nt][2]); v1.y = gelu_f(acc[mt][nt][3]);
            *(float2*)&out[(size_t)(b * NN + r) * DOUT + cl]     = v0;
            *(float2*)&out[(size_t)(b * NN + r + 8) * DOUT + cl] = v1;
        }
    }
}

// ---------------- K4: sum of squares over node axis per (b,d) ---------------
__global__ __launch_bounds__(128) void k4_sumsq(const float* __restrict__ out) {
    const int t = threadIdx.x;
    const int b = blockIdx.y;
    const int ibase = blockIdx.x * 256;
    float s = 0.0f;
    for (int i = 0; i < 256; i++) {
        float v = out[(size_t)(b * NN + ibase + i) * DOUT + t];
        s += v * v;
    }
    atomicAdd(&g_ss[b * DOUT + t], s);
}

// ---------------- K5: L2-normalize over node axis + bias --------------------
__global__ __launch_bounds__(256) void k5_norm(float* __restrict__ out,
                                               const float* __restrict__ bias) {
    int idx = blockIdx.x * 256 + threadIdx.x;
    int d = idx & 127;
    int b = idx >> 19;
    float ss = g_ss[b * DOUT + d];
    float inv = 1.0f / fmaxf(sqrtf(ss), 1e-12f);
    out[idx] = out[idx] * inv + bias[d];
}

// ---------------- launch ----------------------------------------------------
extern "C" void kernel_launch(void* const* d_in, const int* in_sizes, int n_in,
                              void* d_out, int out_size) {
    const float* x    = (const float*)d_in[0];   // [4,4096,256]
    const int*   adj  = (const int*)d_in[1];     // [4,4096,4096]
    const float* w    = (const float*)d_in[2];   // [256,128]
    const float* a    = (const float*)d_in[3];   // [256,1]
    const float* bias = (const float*)d_in[4];   // [128]
    float* out = (float*)d_out;                  // [4,4096,128] fp32

    cudaFuncSetAttribute(k3_pv, cudaFuncAttributeMaxDynamicSharedMemorySize, SMEM_K3);

    k0_zero<<<1, 512>>>();
    k1_h<<<128, 256>>>(x, w);
    k1t_transpose<<<dim3(NN / 32, DOUT / 32, BB), 256>>>();
    k1b_wh<<<64, 256>>>(a);
    k1c_max<<<BB, 1024>>>();
    k2a_stats<<<dim3(8, 8, BB), 128>>>(adj);
    k2b_combine<<<128, 128>>>();
    k3_pv<<<dim3(NN / 128, BB), 256, SMEM_K3>>>(adj, out);
    k4_sumsq<<<dim3(16, BB), 128>>>(out);
    k5_norm<<<8192, 256>>>(out, bias);
}

// round 7
// speedup vs baseline: 2.8208x; 2.3917x over previous
#include <cuda_runtime.h>
#include <cuda_fp16.h>
#include <math.h>
#include <stdint.h>

#define BB   4
#define NN   4096
#define DIN  256
#define DOUT 128

// ---------------- scratch (__device__ globals: allocation-free) -------------
__device__ float  g_h  [BB * NN * DOUT];     // 8 MB : h = x @ W ([b][i][d])
__device__ __half g_p  [(size_t)BB * NN * NN];   // 128M halves = 256 MB : masked exp scores
__device__ __half g_hpT[BB * DOUT * NN];     // 4 MB : fp16 (iz_j * h)^T  ([b][d][j])
__device__ float  g_wh1[BB * NN];
__device__ float  g_wh2[BB * NN];
__device__ float  g_mw1[BB];                 // per-batch max of wh1
__device__ float  g_pz [BB * 32 * NN];       // partial col-sums (32 i-blocks)
__device__ float  g_iz [BB * NN];            // 1 / col-sum
__device__ float  g_ss [BB * DOUT];          // per-(b,d) sum of squares

__device__ __forceinline__ float gelu_f(float x) {
    return 0.5f * x * (1.0f + erff(x * 0.70710678118654752f));
}
// fp16 m16n8k16 HMMA with fp32 accumulate (baseline sm_80+)
__device__ __forceinline__ void mma_f16(float* d, const uint32_t* a, const uint32_t* b) {
    asm volatile("mma.sync.aligned.m16n8k16.row.col.f32.f16.f16.f32 "
                 "{%0,%1,%2,%3}, {%4,%5,%6,%7}, {%8,%9}, {%0,%1,%2,%3};"
                 : "+f"(d[0]), "+f"(d[1]), "+f"(d[2]), "+f"(d[3])
                 : "r"(a[0]), "r"(a[1]), "r"(a[2]), "r"(a[3]),
                   "r"(b[0]), "r"(b[1]));
}
__device__ __forceinline__ uint32_t smem_u32(const void* p) {
    uint32_t a;
    asm("{ .reg .u64 t; cvta.to.shared.u64 t, %1; cvt.u32.u64 %0, t; }" : "=r"(a) : "l"(p));
    return a;
}
#define LDMATRIX_X4(r0, r1, r2, r3, addr) \
    asm volatile("ldmatrix.sync.aligned.m8n8.x4.shared.b16 {%0,%1,%2,%3}, [%4];" \
                 : "=r"(r0), "=r"(r1), "=r"(r2), "=r"(r3) : "r"(addr))
#define LDMATRIX_X2(r0, r1, addr) \
    asm volatile("ldmatrix.sync.aligned.m8n8.x2.shared.b16 {%0,%1}, [%2];" \
                 : "=r"(r0), "=r"(r1) : "r"(addr))

// ---------------- K0: zero sumsq --------------------------------------------
__global__ void k0_zero() {
    int t = threadIdx.x;
    if (t < BB * DOUT) g_ss[t] = 0.0f;
}

// ---------------- K1: h = x @ W  (fp32 FFMA, full precision) ----------------
__global__ __launch_bounds__(256) void k1_h(const float* __restrict__ x,
                                            const float* __restrict__ w) {
    __shared__ float xsT[32 * 129];
    __shared__ float ws[32 * 128];
    const int t = threadIdx.x, lane = t & 31, wrp = t >> 5;
    const int ty = t >> 4, tx = t & 15;
    const int i0 = blockIdx.x * 128;

    float acc[8][8];
#pragma unroll
    for (int r = 0; r < 8; r++)
#pragma unroll
        for (int c = 0; c < 8; c++) acc[r][c] = 0.0f;

    for (int kk = 0; kk < DIN; kk += 32) {
#pragma unroll
        for (int s = 0; s < 16; s++) {
            int ii = wrp + 8 * s;
            xsT[lane * 129 + ii] = x[(i0 + ii) * DIN + kk + lane];
        }
#pragma unroll
        for (int s = 0; s < 16; s++) {
            int idx = t + s * 256;
            int k = idx >> 7, d = idx & 127;
            ws[k * 128 + d] = w[(kk + k) * DOUT + d];
        }
        __syncthreads();
#pragma unroll
        for (int k = 0; k < 32; k++) {
            float aa[8];
#pragma unroll
            for (int r = 0; r < 8; r++) aa[r] = xsT[k * 129 + ty * 8 + r];
            float4 b0 = *(const float4*)&ws[k * 128 + tx * 8];
            float4 b1 = *(const float4*)&ws[k * 128 + tx * 8 + 4];
            float bb[8] = {b0.x, b0.y, b0.z, b0.w, b1.x, b1.y, b1.z, b1.w};
#pragma unroll
            for (int r = 0; r < 8; r++)
#pragma unroll
                for (int c = 0; c < 8; c++)
                    acc[r][c] = fmaf(aa[r], bb[c], acc[r][c]);
        }
        __syncthreads();
    }
#pragma unroll
    for (int r = 0; r < 8; r++) {
        int row = i0 + ty * 8 + r;
        float4 o0, o1;
        o0.x = acc[r][0]; o0.y = acc[r][1]; o0.z = acc[r][2]; o0.w = acc[r][3];
        o1.x = acc[r][4]; o1.y = acc[r][5]; o1.z = acc[r][6]; o1.w = acc[r][7];
        *(float4*)&g_h[row * DOUT + tx * 8]     = o0;
        *(float4*)&g_h[row * DOUT + tx * 8 + 4] = o1;
    }
}

// ---------------- K1b: Wh1/Wh2 — warp per row, float4 + shuffle -------------
__global__ __launch_bounds__(256) void k1b_wh(const float* __restrict__ a) {
    const int t = threadIdx.x, lane = t & 31, wrp = t >> 5;
    const int row = blockIdx.x * 8 + wrp;          // 0..16383
    float4 hv = *(const float4*)&g_h[(size_t)row * DOUT + lane * 4];
    float4 a1 = *(const float4*)&a[lane * 4];
    float4 a2 = *(const float4*)&a[DOUT + lane * 4];
    float s1 = hv.x * a1.x + hv.y * a1.y + hv.z * a1.z + hv.w * a1.w;
    float s2 = hv.x * a2.x + hv.y * a2.y + hv.z * a2.z + hv.w * a2.w;
#pragma unroll
    for (int o = 16; o > 0; o >>= 1) {
        s1 += __shfl_xor_sync(0xffffffffu, s1, o);
        s2 += __shfl_xor_sync(0xffffffffu, s2, o);
    }
    if (lane == 0) { g_wh1[row] = s1; g_wh2[row] = s2; }
}

// ---------------- K1c: maxWh1 per batch -------------------------------------
__global__ __launch_bounds__(1024) void k1c_max() {
    __shared__ float red[32];
    const int b = blockIdx.x, t = threadIdx.x, lane = t & 31, wrp = t >> 5;
    float m = -1e30f;
    for (int i = t; i < NN; i += 1024) m = fmaxf(m, g_wh1[b * NN + i]);
#pragma unroll
    for (int o = 16; o > 0; o >>= 1) m = fmaxf(m, __shfl_xor_sync(0xffffffffu, m, o));
    if (lane == 0) red[wrp] = m;
    __syncthreads();
    if (t < 32) {
        float v = red[t];
#pragma unroll
        for (int o = 16; o > 0; o >>= 1) v = fmaxf(v, __shfl_xor_sync(0xffffffffu, v, o));
        if (t == 0) g_mw1[b] = v;
    }
}

// ---------------- P1: scores -> masked exp (fp16) + partial col sums --------
// Tile 128(i) x 128(j) per block. tx(0..31) covers 4 j each; ty(0..7) strides i.
// e_ij = adj ? exp(gelu(wh1_i + wh2_j) - c_j) : 0, with c_j = max(0, mw1+wh2_j).
__global__ __launch_bounds__(256) void p1_scores(const int* __restrict__ adj) {
    __shared__ float wh1s[128];
    __shared__ float zred[8 * 128];
    const int t = threadIdx.x, tx = t & 31, ty = t >> 5;
    const int b = blockIdx.z, bN = b * NN;
    const int j0 = blockIdx.x * 128, i0 = blockIdx.y * 128;
    const int jj = j0 + 4 * tx;
    const float mw = g_mw1[b];

    float wh2v[4], cv[4], z[4];
#pragma unroll
    for (int u = 0; u < 4; u++) {
        wh2v[u] = g_wh2[bN + jj + u];
        cv[u]   = fmaxf(0.0f, mw + wh2v[u]);
        z[u]    = 0.0f;
    }
    if (t < 128) wh1s[t] = g_wh1[bN + i0 + t];
    __syncthreads();

#pragma unroll 4
    for (int r = 0; r < 16; r++) {
        const int i = i0 + ty + 8 * r;
        const float w1 = wh1s[ty + 8 * r];
        int4 a4 = ((const int4*)(adj + (size_t)(bN + i) * NN))[jj >> 2];
        float e0 = __expf(gelu_f(w1 + wh2v[0]) - cv[0]);
        float e1 = __expf(gelu_f(w1 + wh2v[1]) - cv[1]);
        float e2 = __expf(gelu_f(w1 + wh2v[2]) - cv[2]);
        float e3 = __expf(gelu_f(w1 + wh2v[3]) - cv[3]);
        e0 = (a4.x > 0) ? e0 : 0.0f;
        e1 = (a4.y > 0) ? e1 : 0.0f;
        e2 = (a4.z > 0) ? e2 : 0.0f;
        e3 = (a4.w > 0) ? e3 : 0.0f;
        z[0] += e0; z[1] += e1; z[2] += e2; z[3] += e3;
        __half2 p01 = __floats2half2_rn(e0, e1);
        __half2 p23 = __floats2half2_rn(e2, e3);
        uint2 pw;
        pw.x = *(uint32_t*)&p01;
        pw.y = *(uint32_t*)&p23;
        *(uint2*)(g_p + (size_t)(bN + i) * NN + jj) = pw;
    }
#pragma unroll
    for (int u = 0; u < 4; u++) zred[ty * 128 + 4 * tx + u] = z[u];
    __syncthreads();
    if (t < 128) {
        float s = 0.0f;
#pragma unroll
        for (int u = 0; u < 8; u++) s += zred[u * 128 + t];
        g_pz[(b * 32 + blockIdx.y) * NN + j0 + t] = s;
    }
}

// ---------------- K2b: combine partials -> iz -------------------------------
__global__ __launch_bounds__(128) void k2b_combine() {
    int c = blockIdx.x * 128 + threadIdx.x;        // b*NN + j
    int b = c >> 12, j = c & (NN - 1);
    float Z = 0.0f;
#pragma unroll
    for (int u = 0; u < 32; u++) Z += g_pz[(b * 32 + u) * NN + j];
    g_iz[c] = 1.0f / fmaxf(Z, 1e-6f);
}

// ---------------- HS: g_hpT[b][d][j] = fp16( iz_j * h[b][j][d] ) ------------
__global__ __launch_bounds__(256) void hscaleT() {
    __shared__ float ts[32][33];
    __shared__ float izs[32];
    const int t = threadIdx.x, lx = t & 31, ly = t >> 5;
    const int j0 = blockIdx.x * 32, d0 = blockIdx.y * 32, b = blockIdx.z;
    if (t < 32) izs[t] = g_iz[b * NN + j0 + t];
#pragma unroll
    for (int s = 0; s < 4; s++)
        ts[ly + 8 * s][lx] = g_h[(size_t)(b * NN + j0 + ly + 8 * s) * DOUT + d0 + lx];
    __syncthreads();
#pragma unroll
    for (int s = 0; s < 4; s++)
        g_hpT[(size_t)(b * DOUT + d0 + ly + 8 * s) * NN + j0 + lx] =
            __float2half(ts[lx][ly + 8 * s] * izs[lx]);
}

// ---------------- K3: out = gelu(E @ h') — pure fp16 HMMA GEMM --------------
// Block 128(i) x 128(d); K chunks of 32; 8 warps (2m x 4n), warp 64x32 as
// 4x2 m16n8k16 steps x 4 n-tiles. SMEM rows padded to 40 halves (stride 80 B):
// conflict-free for both uint4 staging and ldmatrix phases.
#define PADH 40
#define ST_A0 0
#define ST_A1 5120
#define ST_B0 10240
#define ST_B1 15360

__global__ __launch_bounds__(256) void k3_pv(float* __restrict__ out) {
    __shared__ __half sm[4 * 5120];                // 40 KB
    const uint32_t sbase = smem_u32(sm);
    const int t = threadIdx.x, lane = t & 31, wrp = t >> 5;
    const int g = lane >> 2, tg = lane & 3;
    const int b = blockIdx.y, bN = b * NN;
    const int i0 = blockIdx.x * 128;
    const int m_base = (wrp >> 2) * 64;
    const int n_base = (wrp & 3) * 32;
    // ldmatrix per-thread address components
    const int rowA = m_base + (lane & 15);
    const int colA = (lane >> 4) << 3;             // 0 or 8 (halves)
    const int rowB = n_base + (lane & 7);
    const int colB = lane & 8;                     // 0 or 8 (halves)
    // staging components (row/seg of the 128x32 tile)
    const int srow = t >> 2, sseg = t & 3;
    const __half* gA = g_p   + (size_t)(bN + i0 + srow) * NN + sseg * 8;
    const __half* gB = g_hpT + (size_t)(b * DOUT + srow) * NN + sseg * 8;
    __half* stA = sm + srow * PADH + sseg * 8;
    __half* stB = sm + ST_B0 + srow * PADH + sseg * 8;

    float acc[4][4][4];
#pragma unroll
    for (int mt = 0; mt < 4; mt++)
#pragma unroll
        for (int nt = 0; nt < 4; nt++)
#pragma unroll
            for (int q = 0; q < 4; q++) acc[mt][nt][q] = 0.0f;

    // fill stage 0 (kt = 0): rows srow and srow+64 (two passes of 64 rows? no:
    // 256 threads x 2 iters cover 128 rows x 4 segs)
#pragma unroll
    for (int s = 0; s < 2; s++) {
        *(uint4*)(stA + s * 64 * PADH) = *(const uint4*)(gA + (size_t)(s * 64) * NN);
        *(uint4*)(stB + s * 64 * PADH) = *(const uint4*)(gB + (size_t)(s * 64) * NN);
    }
    __syncthreads();

    for (int kt = 0; kt < 128; kt++) {
        const int cur = kt & 1;
        // overlap: fill next stage while issuing mma on current
        if (kt + 1 < 128) {
            const int kb = (kt + 1) * 32;
            __half* dA = sm + (cur ? ST_A0 : ST_A1) + srow * PADH + sseg * 8;
            __half* dB = sm + (cur ? ST_B0 + 0 : ST_B1) + srow * PADH + sseg * 8;
            // note: cur==0 -> next stage is 1
            dA = sm + (cur ? ST_A0 : ST_A1) + srow * PADH + sseg * 8;
            dB = sm + (cur ? ST_B0 : ST_B1) + srow * PADH + sseg * 8;
#pragma unroll
            for (int s = 0; s < 2; s++) {
                *(uint4*)(dA + s * 64 * PADH) = *(const uint4*)(gA + kb + (size_t)(s * 64) * NN);
                *(uint4*)(dB + s * 64 * PADH) = *(const uint4*)(gB + kb + (size_t)(s * 64) * NN);
            }
        }
        const uint32_t sA = sbase + (cur ? ST_A1 : ST_A0) * 2;
        const uint32_t sB = sbase + (cur ? ST_B1 : ST_B0) * 2;
#pragma unroll
        for (int ks = 0; ks < 2; ks++) {
            const int k0 = ks * 16;
            uint32_t af[4][4], bf[4][2];
#pragma unroll
            for (int mt = 0; mt < 4; mt++)
                LDMATRIX_X4(af[mt][0], af[mt][1], af[mt][2], af[mt][3],
                            sA + ((rowA + mt * 16) * PADH + k0 + colA) * 2);
#pragma unroll
            for (int nt = 0; nt < 4; nt++)
                LDMATRIX_X2(bf[nt][0], bf[nt][1],
                            sB + ((rowB + nt * 8) * PADH + k0 + colB) * 2);
#pragma unroll
            for (int mt = 0; mt < 4; mt++)
#pragma unroll
                for (int nt = 0; nt < 4; nt++)
                    mma_f16(acc[mt][nt], af[mt], bf[nt]);
        }
        __syncthreads();
    }

    // epilogue: gelu + float2 stores
    const float gelu_c = 0.70710678118654752f;
#pragma unroll
    for (int mt = 0; mt < 4; mt++) {
        int r = i0 + m_base + mt * 16 + g;
#pragma unroll
        for (int nt = 0; nt < 4; nt++) {
            int cl = n_base + nt * 8 + 2 * tg;
            float2 v0, v1;
            v0.x = gelu_f(acc[mt][nt][0]); v0.y = gelu_f(acc[mt][nt][1]);
            v1.x = gelu_f(acc[mt][nt][2]); v1.y = gelu_f(acc[mt][nt][3]);
            *(float2*)&out[(size_t)(bN + r) * DOUT + cl]     = v0;
            *(float2*)&out[(size_t)(bN + r + 8) * DOUT + cl] = v1;
        }
    }
    (void)gelu_c;
}

// ---------------- K4: sum of squares over node axis per (b,d) ---------------
__global__ __launch_bounds__(128) void k4_sumsq(const float* __restrict__ out) {
    const int t = threadIdx.x;
    const int b = blockIdx.y;
    const int ibase = blockIdx.x * 256;
    float s = 0.0f;
    for (int i = 0; i < 256; i++) {
        float v = out[(size_t)(b * NN + ibase + i) * DOUT + t];
        s += v * v;
    }
    atomicAdd(&g_ss[b * DOUT + t], s);
}

// ---------------- K5: L2-normalize over node axis + bias --------------------
__global__ __launch_bounds__(256) void k5_norm(float* __restrict__ out,
                                               const float* __restrict__ bias) {
    int idx = blockIdx.x * 256 + threadIdx.x;
    int d = idx & 127;
    int b = idx >> 19;
    float ss = g_ss[b * DOUT + d];
    float inv = 1.0f / fmaxf(sqrtf(ss), 1e-12f);
    out[idx] = out[idx] * inv + bias[d];
}

// ---------------- launch ----------------------------------------------------
extern "C" void kernel_launch(void* const* d_in, const int* in_sizes, int n_in,
                              void* d_out, int out_size) {
    const float* x    = (const float*)d_in[0];   // [4,4096,256]
    const int*   adj  = (const int*)d_in[1];     // [4,4096,4096]
    const float* w    = (const float*)d_in[2];   // [256,128]
    const float* a    = (const float*)d_in[3];   // [256,1]
    const float* bias = (const float*)d_in[4];   // [128]
    float* out = (float*)d_out;                  // [4,4096,128] fp32

    k0_zero<<<1, 512>>>();
    k1_h<<<128, 256>>>(x, w);
    k1b_wh<<<2048, 256>>>(a);
    k1c_max<<<BB, 1024>>>();
    p1_scores<<<dim3(NN / 128, NN / 128, BB), 256>>>(adj);
    k2b_combine<<<128, 128>>>();
    hscaleT<<<dim3(NN / 32, DOUT / 32, BB), 256>>>();
    k3_pv<<<dim3(NN / 128, BB), 256>>>(out);
    k4_sumsq<<<dim3(16, BB), 128>>>(out);
    k5_norm<<<8192, 256>>>(out, bias);
}